// round 11
// baseline (speedup 1.0000x reference)
#include <cuda_runtime.h>
#include <cstdint>

#define NN 200000
#define EE 400000
#define EPN 100000
#define HH 256

// ---------------- device scratch ----------------
__device__ float g_agg[(size_t)NN * HH];
__device__ float g_zinA[(size_t)NN * HH];
__device__ float g_zinB[(size_t)NN * HH];
__device__ float g_zactA[(size_t)NN * HH];
__device__ float g_zactB[(size_t)NN * HH];
__device__ float g_s[(size_t)EPN * HH];
__device__ float g_h[(size_t)EPN * HH];
__device__ float g_wt_hi[256 * 512];
__device__ float g_wt_lo[256 * 512];
__device__ float g_wtB_hi[256 * 256];
__device__ float g_wtB_lo[256 * 256];
__device__ float g_wtO_hi[256 * 256];
__device__ float g_wtO_lo[256 * 256];

// ---------------- helpers ----------------
__device__ __forceinline__ float lrelu(float v) { return v >= 0.f ? v : 0.01f * v; }
__device__ __forceinline__ float tf32_hi(float a) {
    return __uint_as_float(__float_as_uint(a) & 0xFFFFE000u);
}
__device__ __forceinline__ uint32_t smem_u32(const void* p) {
    uint32_t a;
    asm("{ .reg .u64 t; cvta.to.shared.u64 t, %1; cvt.u32.u64 %0, t; }" : "=r"(a) : "l"(p));
    return a;
}
__device__ __forceinline__ void cpasync16(uint32_t dst, const void* src) {
    asm volatile("cp.async.ca.shared.global [%0], [%1], 16;" :: "r"(dst), "l"(src));
}
#define CP_COMMIT() asm volatile("cp.async.commit_group;" ::: "memory")
#define CP_WAIT0()  asm volatile("cp.async.wait_group 0;" ::: "memory")

#define LDSM4(r, a)                                                            \
    asm volatile("ldmatrix.sync.aligned.m8n8.x4.shared.b16 {%0,%1,%2,%3}, [%4];" \
                 : "=r"((r)[0]), "=r"((r)[1]), "=r"((r)[2]), "=r"((r)[3]) : "r"(a))
#define LDSM2(r, a)                                                            \
    asm volatile("ldmatrix.sync.aligned.m8n8.x2.shared.b16 {%0,%1}, [%2];"     \
                 : "=r"((r)[0]), "=r"((r)[1]) : "r"(a))

__device__ __forceinline__ void mma_tf32(float* d, const uint32_t* a, const uint32_t* b) {
    asm volatile("mma.sync.aligned.m16n8k8.row.col.f32.tf32.tf32.f32 "
                 "{%0,%1,%2,%3},{%4,%5,%6,%7},{%8,%9},{%0,%1,%2,%3};"
                 : "+f"(d[0]), "+f"(d[1]), "+f"(d[2]), "+f"(d[3])
                 : "r"(a[0]), "r"(a[1]), "r"(a[2]), "r"(a[3]), "r"(b[0]), "r"(b[1]));
}

// ---------------- 3xTF32 mma.sync GEMM ----------------
// C[rows x 256] = act([A1|A2] @ WT^T + bias*bscale); WT pre-split [256][Kt] k-contig
#define BK 32
#define LDA 36
#define TILE_F (128 * LDA)       // 4608 floats
#define STAGE_F (4 * TILE_F)     // Ah, Al, Bh, Bl
#define GM_SMEM (2 * STAGE_F * 4)

__global__ void __launch_bounds__(256, 1) gemm_mma(
    const float* __restrict__ A1, const float* __restrict__ A2,
    int K1, int Kt,
    const float* __restrict__ WTh, const float* __restrict__ WTl,
    const float* __restrict__ bias, float bscale,
    const float* __restrict__ addend,
    float* __restrict__ out_act, float* __restrict__ out_next,
    int rows)
{
    extern __shared__ float sm[];
    const int tid  = threadIdx.x;
    const int lane = tid & 31;
    const int wid  = tid >> 5;
    const int wm   = wid & 1;       // 2 warps along M (64 rows each)
    const int wn   = wid >> 1;      // 4 warps along N (32 cols each)
    const int bm   = blockIdx.x * 128;
    const int bn   = blockIdx.y * 128;
    const int NC   = Kt >> 5;
    const int K2   = Kt - K1;

    const uint32_t smb = smem_u32(sm);

    // A gmem load mapping: thread -> (row, 16-float half)
    const int arow  = tid >> 1;
    const int acolb = (tid & 1) * 16;
    const int grow  = bm + arow;
    const bool rowok = grow < rows;

    // ldmatrix lane offsets (floats)
    const int aq = lane >> 3, ar = lane & 7;
    const uint32_t a_lane = (uint32_t)((wm * 64 + (aq & 1) * 8 + ar) * LDA + (aq >> 1) * 4);
    const int t4 = lane & 15;
    const uint32_t b_lane = (uint32_t)((wn * 32 + (t4 & 7)) * LDA + (t4 >> 3) * 4);

    float acc[4][4][4];
#pragma unroll
    for (int mt = 0; mt < 4; mt++)
#pragma unroll
        for (int nt = 0; nt < 4; nt++)
#pragma unroll
            for (int j = 0; j < 4; j++) acc[mt][nt][j] = 0.f;

    float4 areg[4];

    auto loadA = [&](int c) {
        const int k0 = c * BK;
        const float* Ap;
        int stride, koff;
        if (k0 < K1) { Ap = A1; stride = K1; koff = k0; }
        else         { Ap = A2; stride = K2; koff = k0 - K1; }
        const float* src = Ap + (size_t)grow * stride + koff + acolb;
#pragma unroll
        for (int j = 0; j < 4; j++)
            areg[j] = rowok ? *(const float4*)(src + j * 4)
                            : make_float4(0.f, 0.f, 0.f, 0.f);
    };
    auto storeA = [&](int s) {
        float* Ah = sm + s * STAGE_F;
        float* Al = Ah + TILE_F;
        const int doff = arow * LDA + acolb;
#pragma unroll
        for (int j = 0; j < 4; j++) {
            float4 v = areg[j], h, l;
            h.x = tf32_hi(v.x); l.x = v.x - h.x;
            h.y = tf32_hi(v.y); l.y = v.y - h.y;
            h.z = tf32_hi(v.z); l.z = v.z - h.z;
            h.w = tf32_hi(v.w); l.w = v.w - h.w;
            *(float4*)(Ah + doff + j * 4) = h;
            *(float4*)(Al + doff + j * 4) = l;
        }
    };
    auto loadB = [&](int c, int s) {
        const int k0 = c * BK;
        const uint32_t bhb = smb + (uint32_t)((s * STAGE_F + 2 * TILE_F) * 4);
        const uint32_t blb = bhb + TILE_F * 4;
#pragma unroll
        for (int i = 0; i < 4; i++) {
            int q = i * 256 + tid;          // 0..1023
            int row = q >> 3, c16 = q & 7;
            size_t goff = (size_t)(bn + row) * Kt + k0 + c16 * 4;
            uint32_t doff = (uint32_t)((row * LDA + c16 * 4) * 4);
            cpasync16(bhb + doff, WTh + goff);
            cpasync16(blb + doff, WTl + goff);
        }
    };
    auto compute = [&](int s) {
        const uint32_t ahb = smb + (uint32_t)(s * STAGE_F * 4);
        const uint32_t bhb = ahb + (uint32_t)(2 * TILE_F * 4);
#pragma unroll
        for (int ks = 0; ks < 4; ks++) {
            uint32_t ah[4][4], al[4][4], bh[4][2], bl[4][2];
#pragma unroll
            for (int mt = 0; mt < 4; mt++) {
                uint32_t ad = ahb + (a_lane + (uint32_t)(mt * 16 * LDA + ks * 8)) * 4;
                LDSM4(ah[mt], ad);
                LDSM4(al[mt], ad + TILE_F * 4);
            }
#pragma unroll
            for (int nt = 0; nt < 4; nt++) {
                uint32_t bd = bhb + (b_lane + (uint32_t)(nt * 8 * LDA + ks * 8)) * 4;
                LDSM2(bh[nt], bd);
                LDSM2(bl[nt], bd + TILE_F * 4);
            }
#pragma unroll
            for (int mt = 0; mt < 4; mt++)
#pragma unroll
                for (int nt = 0; nt < 4; nt++) {
                    mma_tf32(acc[mt][nt], ah[mt], bh[nt]);
                    mma_tf32(acc[mt][nt], ah[mt], bl[nt]);
                    mma_tf32(acc[mt][nt], al[mt], bh[nt]);
                }
        }
    };

    // pipeline
    loadA(0);
    loadB(0, 0);
    CP_COMMIT();
    storeA(0);
    CP_WAIT0();
    __syncthreads();
    for (int c = 0; c < NC; c++) {
        const int s = c & 1, ns = s ^ 1;
        if (c + 1 < NC) {
            loadA(c + 1);
            loadB(c + 1, ns);
            CP_COMMIT();
        }
        compute(s);
        if (c + 1 < NC) {
            storeA(ns);
            CP_WAIT0();
        }
        __syncthreads();
    }

    // epilogue
#pragma unroll
    for (int mt = 0; mt < 4; mt++) {
#pragma unroll
        for (int nt = 0; nt < 4; nt++) {
            const int r0 = bm + wm * 64 + mt * 16 + (lane >> 2);
            const int cb = bn + wn * 32 + nt * 8 + (lane & 3) * 2;
            const float b0 = bias[cb] * bscale;
            const float b1 = bias[cb + 1] * bscale;
#pragma unroll
            for (int half = 0; half < 2; half++) {
                const int r = r0 + half * 8;
                if (r >= rows) continue;
                const float v0 = acc[mt][nt][half * 2 + 0] + b0;
                const float v1 = acc[mt][nt][half * 2 + 1] + b1;
                float2 o = make_float2(lrelu(v0), lrelu(v1));
                const size_t base = (size_t)r * HH + cb;
                if (out_act) *(float2*)(out_act + base) = o;
                if (out_next) {
                    float2 nx = o;
                    if (addend) {
                        float2 ad = *(const float2*)(addend + base);
                        nx.x += ad.x; nx.y += ad.y;
                    }
                    *(float2*)(out_next + base) = nx;
                }
            }
        }
    }
}

// ---------------- weight prep: transpose + tf32 split ----------------
__global__ void prep_conv(const float* __restrict__ W1, int K1,
                          const float* __restrict__ W2, int K2,
                          float* __restrict__ wh, float* __restrict__ wl)
{
    const int Kt  = K1 + K2;
    const int idx = blockIdx.x * 256 + threadIdx.x;
    if (idx >= 256 * Kt) return;
    const int n = idx / Kt, k = idx % Kt;
    const float v = (k < K1) ? W1[(size_t)k * 256 + n] : W2[(size_t)(k - K1) * 256 + n];
    const float h = tf32_hi(v);
    wh[idx] = h;
    wl[idx] = v - h;
}

__global__ void prep_head(const float* __restrict__ w0,
                          float* __restrict__ wh, float* __restrict__ wl)
{
    const int idx = blockIdx.x * 256 + threadIdx.x;
    const int n = idx >> 8, k = idx & 255;
    const float v = w0[(size_t)k * 256 + n] + w0[(size_t)(k + 256) * 256 + n];
    const float h = tf32_hi(v);
    wh[idx] = h;
    wl[idx] = v - h;
}

// ---------------- zero ----------------
__global__ void zero_kernel(float* __restrict__ p, long n)
{
    long i = ((long)blockIdx.x * blockDim.x + threadIdx.x) << 2;
    if (i < n) *(float4*)(p + i) = make_float4(0.f, 0.f, 0.f, 0.f);
}

// ---------------- scatter ----------------
__global__ void scatter_kernel(const float* __restrict__ z, const int* __restrict__ ei,
                               float* __restrict__ agg, int F, int shift)
{
    long tid = (long)blockIdx.x * blockDim.x + threadIdx.x;
    long e   = tid >> shift;
    if (e >= EE) return;
    int f    = (int)(tid & ((1 << shift) - 1)) << 2;
    int sidx = ei[e];
    int d    = ei[EE + e];
    float4 v = *(const float4*)(z + (size_t)sidx * F + f);
    const float* a = agg + (size_t)d * F + f;
    asm volatile("red.global.add.v4.f32 [%0], {%1, %2, %3, %4};"
                 :: "l"(a), "f"(v.x), "f"(v.y), "f"(v.z), "f"(v.w)
                 : "memory");
}

// ---------------- gather ----------------
__global__ void gather_kernel(const float* __restrict__ z, const int* __restrict__ etp,
                              float* __restrict__ s)
{
    long tid = (long)blockIdx.x * blockDim.x + threadIdx.x;
    long e   = tid >> 6;
    if (e >= EPN) return;
    int f = (int)(tid & 63) << 2;
    int a = etp[e * 2 + 0];
    int b = etp[e * 2 + 1];
    float4 va = *(const float4*)(z + (size_t)a * HH + f);
    float4 vb = *(const float4*)(z + (size_t)b * HH + f);
    va.x += vb.x; va.y += vb.y; va.z += vb.z; va.w += vb.w;
    *(float4*)(s + (size_t)e * HH + f) = va;
}

// ---------------- projection ----------------
__global__ void proj_kernel(const float* __restrict__ h, const float* __restrict__ w,
                            const float* __restrict__ b, float* __restrict__ out,
                            int M, int rows)
{
    int gw   = (int)(((long)blockIdx.x * blockDim.x + threadIdx.x) >> 5);
    int lane = threadIdx.x & 31;
    if (gw >= rows) return;
    const float* hr = h + (size_t)gw * HH;
    float a0 = 0.f, a1 = 0.f, a2 = 0.f;
    int k0 = lane << 3;
#pragma unroll
    for (int i = 0; i < 8; i++) {
        int k    = k0 + i;
        float hv = hr[k];
        a0 += hv * w[k * M + 0];
        if (M > 1) {
            a1 += hv * w[k * M + 1];
            a2 += hv * w[k * M + 2];
        }
    }
#pragma unroll
    for (int off = 16; off; off >>= 1) {
        a0 += __shfl_xor_sync(0xffffffffu, a0, off);
        a1 += __shfl_xor_sync(0xffffffffu, a1, off);
        a2 += __shfl_xor_sync(0xffffffffu, a2, off);
    }
    if (lane == 0) {
        out[(size_t)gw * M + 0] = a0 + b[0];
        if (M > 1) {
            out[(size_t)gw * M + 1] = a1 + b[1];
            out[(size_t)gw * M + 2] = a2 + b[2];
        }
    }
}

// ---------------- launch ----------------
extern "C" void kernel_launch(void* const* d_in, const int* in_sizes, int n_in,
                              void* d_out, int out_size)
{
    const float* x   = (const float*)d_in[0];
    const int*   ei  = (const int*)d_in[1];
    const int*   etp = (const int*)d_in[2];
    const float* wrel[4]  = {(const float*)d_in[3],  (const float*)d_in[6],
                             (const float*)d_in[9],  (const float*)d_in[12]};
    const float* brel[4]  = {(const float*)d_in[4],  (const float*)d_in[7],
                             (const float*)d_in[10], (const float*)d_in[13]};
    const float* wroot[4] = {(const float*)d_in[5],  (const float*)d_in[8],
                             (const float*)d_in[11], (const float*)d_in[14]};
    const float* wb0 = (const float*)d_in[15];
    const float* bb0 = (const float*)d_in[16];
    const float* wb1 = (const float*)d_in[17];
    const float* bb1 = (const float*)d_in[18];
    const float* wo0 = (const float*)d_in[19];
    const float* bo0 = (const float*)d_in[20];
    const float* wo1 = (const float*)d_in[21];
    const float* bo1 = (const float*)d_in[22];
    float* out = (float*)d_out;

    float *agg, *zinA, *zinB, *zactA, *zactB, *s, *h;
    float *wth, *wtl, *wtBh, *wtBl, *wtOh, *wtOl;
    cudaGetSymbolAddress((void**)&agg,   g_agg);
    cudaGetSymbolAddress((void**)&zinA,  g_zinA);
    cudaGetSymbolAddress((void**)&zinB,  g_zinB);
    cudaGetSymbolAddress((void**)&zactA, g_zactA);
    cudaGetSymbolAddress((void**)&zactB, g_zactB);
    cudaGetSymbolAddress((void**)&s,     g_s);
    cudaGetSymbolAddress((void**)&h,     g_h);
    cudaGetSymbolAddress((void**)&wth,   g_wt_hi);
    cudaGetSymbolAddress((void**)&wtl,   g_wt_lo);
    cudaGetSymbolAddress((void**)&wtBh,  g_wtB_hi);
    cudaGetSymbolAddress((void**)&wtBl,  g_wtB_lo);
    cudaGetSymbolAddress((void**)&wtOh,  g_wtO_hi);
    cudaGetSymbolAddress((void**)&wtOl,  g_wtO_lo);

    cudaFuncSetAttribute(gemm_mma, cudaFuncAttributeMaxDynamicSharedMemorySize, GM_SMEM);

    dim3 gconv((NN + 127) / 128, 2);
    dim3 ghead((EPN + 127) / 128, 2);

    long z128 = (long)NN * 128, z256 = (long)NN * 256;
    int  zb128 = (int)((z128 / 4 + 255) / 256);
    int  zb256 = (int)((z256 / 4 + 255) / 256);
    int  sc128 = (int)(((long)EE * 32 + 255) / 256);
    int  sc256 = (int)(((long)EE * 64 + 255) / 256);

    // Layer 0: z0 = act(agg(x)@wr0 + b0 + x@wroot0); zinA = z0; zactA = z0
    prep_conv<<<(256 * 256 + 255) / 256, 256>>>(wrel[0], 128, wroot[0], 128, wth, wtl);
    zero_kernel<<<zb128, 256>>>(agg, z128);
    scatter_kernel<<<sc128, 256>>>(x, ei, agg, 128, 5);
    gemm_mma<<<gconv, 256, GM_SMEM>>>(agg, x, 128, 256, wth, wtl, brel[0], 1.f,
                                      nullptr, zactA, zinA, NN);
    // Layer 1: z1; zinB = z1 + z0; zactB = z1
    prep_conv<<<(256 * 512 + 255) / 256, 256>>>(wrel[1], 256, wroot[1], 256, wth, wtl);
    zero_kernel<<<zb256, 256>>>(agg, z256);
    scatter_kernel<<<sc256, 256>>>(zinA, ei, agg, 256, 6);
    gemm_mma<<<gconv, 256, GM_SMEM>>>(agg, zinA, 256, 512, wth, wtl, brel[1], 1.f,
                                      zactA, zactB, zinB, NN);
    // Layer 2: z2; zinA = z2 + z1; zactA = z2
    prep_conv<<<(256 * 512 + 255) / 256, 256>>>(wrel[2], 256, wroot[2], 256, wth, wtl);
    zero_kernel<<<zb256, 256>>>(agg, z256);
    scatter_kernel<<<sc256, 256>>>(zinB, ei, agg, 256, 6);
    gemm_mma<<<gconv, 256, GM_SMEM>>>(agg, zinB, 256, 512, wth, wtl, brel[2], 1.f,
                                      zactB, zactA, zinA, NN);
    // Layer 3: z3; zinB = z3 + z2 (addend = zactA)
    prep_conv<<<(256 * 512 + 255) / 256, 256>>>(wrel[3], 256, wroot[3], 256, wth, wtl);
    zero_kernel<<<zb256, 256>>>(agg, z256);
    scatter_kernel<<<sc256, 256>>>(zinA, ei, agg, 256, 6);
    gemm_mma<<<gconv, 256, GM_SMEM>>>(agg, zinA, 256, 512, wth, wtl, brel[3], 1.f,
                                      zactA, nullptr, zinB, NN);

    // Edge features: s = z[a] + z[b]
    gather_kernel<<<(int)(((long)EPN * 64 + 255) / 256), 256>>>(zinB, etp, s);

    // Heads
    prep_head<<<(256 * 256 + 255) / 256, 256>>>(wb0, wtBh, wtBl);
    prep_head<<<(256 * 256 + 255) / 256, 256>>>(wo0, wtOh, wtOl);
    gemm_mma<<<ghead, 256, GM_SMEM>>>(s, s, 256, 256, wtBh, wtBl, bb0, 2.f,
                                      nullptr, h, nullptr, EPN);
    proj_kernel<<<(int)(((long)EPN * 32 + 255) / 256), 256>>>(h, wb1, bb1,
                                                              out + 3 * EPN, 1, EPN);
    gemm_mma<<<ghead, 256, GM_SMEM>>>(s, s, 256, 256, wtOh, wtOl, bo0, 2.f,
                                      nullptr, h, nullptr, EPN);
    proj_kernel<<<(int)(((long)EPN * 32 + 255) / 256), 256>>>(h, wo1, bo1,
                                                              out, 3, EPN);
}

// round 12
// speedup vs baseline: 1.0001x; 1.0001x over previous
#include <cuda_runtime.h>
#include <cstdint>

#define NN 200000
#define EE 400000
#define EPN 100000
#define HH 256

// ---------------- device scratch ----------------
__device__ float g_agg[(size_t)NN * HH];
__device__ float g_zinA[(size_t)NN * HH];
__device__ float g_zinB[(size_t)NN * HH];
__device__ float g_zactA[(size_t)NN * HH];
__device__ float g_zactB[(size_t)NN * HH];
__device__ float g_s[(size_t)EPN * HH];
__device__ float g_h[(size_t)EPN * HH];
__device__ float g_wt_hi[256 * 512];
__device__ float g_wt_lo[256 * 512];
__device__ float g_wtB_hi[256 * 256];
__device__ float g_wtB_lo[256 * 256];
__device__ float g_wtO_hi[256 * 256];
__device__ float g_wtO_lo[256 * 256];

// ---------------- helpers ----------------
__device__ __forceinline__ float lrelu(float v) { return v >= 0.f ? v : 0.01f * v; }
__device__ __forceinline__ float tf32_hi(float a) {
    return __uint_as_float(__float_as_uint(a) & 0xFFFFE000u);
}
__device__ __forceinline__ uint32_t smem_u32(const void* p) {
    uint32_t a;
    asm("{ .reg .u64 t; cvta.to.shared.u64 t, %1; cvt.u32.u64 %0, t; }" : "=r"(a) : "l"(p));
    return a;
}
__device__ __forceinline__ void cpasync16(uint32_t dst, const void* src) {
    asm volatile("cp.async.ca.shared.global [%0], [%1], 16;" :: "r"(dst), "l"(src));
}
#define CP_COMMIT() asm volatile("cp.async.commit_group;" ::: "memory")
#define CP_WAIT0()  asm volatile("cp.async.wait_group 0;" ::: "memory")

#define LDSM4(r, a)                                                            \
    asm volatile("ldmatrix.sync.aligned.m8n8.x4.shared.b16 {%0,%1,%2,%3}, [%4];" \
                 : "=r"((r)[0]), "=r"((r)[1]), "=r"((r)[2]), "=r"((r)[3]) : "r"(a))
#define LDSM2(r, a)                                                            \
    asm volatile("ldmatrix.sync.aligned.m8n8.x2.shared.b16 {%0,%1}, [%2];"     \
                 : "=r"((r)[0]), "=r"((r)[1]) : "r"(a))

__device__ __forceinline__ void mma_tf32(float* d, const uint32_t* a, const uint32_t* b) {
    asm volatile("mma.sync.aligned.m16n8k8.row.col.f32.tf32.tf32.f32 "
                 "{%0,%1,%2,%3},{%4,%5,%6,%7},{%8,%9},{%0,%1,%2,%3};"
                 : "+f"(d[0]), "+f"(d[1]), "+f"(d[2]), "+f"(d[3])
                 : "r"(a[0]), "r"(a[1]), "r"(a[2]), "r"(a[3]), "r"(b[0]), "r"(b[1]));
}

// ---------------- 3xTF32 mma.sync GEMM ----------------
// C[rows x 256] = act([A1|A2] @ WT^T + bias*bscale); WT pre-split [256][Kt] k-contig
#define BK 32
#define LDA 36
#define TILE_F (128 * LDA)       // 4608 floats
#define STAGE_F (4 * TILE_F)     // Ah, Al, Bh, Bl
#define GM_SMEM (2 * STAGE_F * 4)

__global__ void __launch_bounds__(256, 1) gemm_mma(
    const float* __restrict__ A1, const float* __restrict__ A2,
    int K1, int Kt,
    const float* __restrict__ WTh, const float* __restrict__ WTl,
    const float* __restrict__ bias, float bscale,
    const float* __restrict__ addend,
    float* __restrict__ out_act, float* __restrict__ out_next,
    int rows)
{
    extern __shared__ float sm[];
    const int tid  = threadIdx.x;
    const int lane = tid & 31;
    const int wid  = tid >> 5;
    const int wm   = wid & 1;       // 2 warps along M (64 rows each)
    const int wn   = wid >> 1;      // 4 warps along N (32 cols each)
    const int bm   = blockIdx.x * 128;
    const int bn   = blockIdx.y * 128;
    const int NC   = Kt >> 5;
    const int K2   = Kt - K1;

    const uint32_t smb = smem_u32(sm);

    // A gmem load mapping: thread -> (row, 16-float half)
    const int arow  = tid >> 1;
    const int acolb = (tid & 1) * 16;
    const int grow  = bm + arow;
    const bool rowok = grow < rows;

    // ldmatrix lane offsets (floats)
    const int aq = lane >> 3, ar = lane & 7;
    const uint32_t a_lane = (uint32_t)((wm * 64 + (aq & 1) * 8 + ar) * LDA + (aq >> 1) * 4);
    const int t4 = lane & 15;
    const uint32_t b_lane = (uint32_t)((wn * 32 + (t4 & 7)) * LDA + (t4 >> 3) * 4);

    float acc[4][4][4];
#pragma unroll
    for (int mt = 0; mt < 4; mt++)
#pragma unroll
        for (int nt = 0; nt < 4; nt++)
#pragma unroll
            for (int j = 0; j < 4; j++) acc[mt][nt][j] = 0.f;

    float4 areg[4];

    auto loadA = [&](int c) {
        const int k0 = c * BK;
        const float* Ap;
        int stride, koff;
        if (k0 < K1) { Ap = A1; stride = K1; koff = k0; }
        else         { Ap = A2; stride = K2; koff = k0 - K1; }
        const float* src = Ap + (size_t)grow * stride + koff + acolb;
#pragma unroll
        for (int j = 0; j < 4; j++)
            areg[j] = rowok ? *(const float4*)(src + j * 4)
                            : make_float4(0.f, 0.f, 0.f, 0.f);
    };
    auto storeA = [&](int s) {
        float* Ah = sm + s * STAGE_F;
        float* Al = Ah + TILE_F;
        const int doff = arow * LDA + acolb;
#pragma unroll
        for (int j = 0; j < 4; j++) {
            float4 v = areg[j], h, l;
            h.x = tf32_hi(v.x); l.x = v.x - h.x;
            h.y = tf32_hi(v.y); l.y = v.y - h.y;
            h.z = tf32_hi(v.z); l.z = v.z - h.z;
            h.w = tf32_hi(v.w); l.w = v.w - h.w;
            *(float4*)(Ah + doff + j * 4) = h;
            *(float4*)(Al + doff + j * 4) = l;
        }
    };
    auto loadB = [&](int c, int s) {
        const int k0 = c * BK;
        const uint32_t bhb = smb + (uint32_t)((s * STAGE_F + 2 * TILE_F) * 4);
        const uint32_t blb = bhb + TILE_F * 4;
#pragma unroll
        for (int i = 0; i < 4; i++) {
            int q = i * 256 + tid;          // 0..1023
            int row = q >> 3, c16 = q & 7;
            size_t goff = (size_t)(bn + row) * Kt + k0 + c16 * 4;
            uint32_t doff = (uint32_t)((row * LDA + c16 * 4) * 4);
            cpasync16(bhb + doff, WTh + goff);
            cpasync16(blb + doff, WTl + goff);
        }
    };
    auto compute = [&](int s) {
        const uint32_t ahb = smb + (uint32_t)(s * STAGE_F * 4);
        const uint32_t bhb = ahb + (uint32_t)(2 * TILE_F * 4);
#pragma unroll
        for (int ks = 0; ks < 4; ks++) {
            uint32_t ah[4][4], al[4][4], bh[4][2], bl[4][2];
#pragma unroll
            for (int mt = 0; mt < 4; mt++) {
                uint32_t ad = ahb + (a_lane + (uint32_t)(mt * 16 * LDA + ks * 8)) * 4;
                LDSM4(ah[mt], ad);
                LDSM4(al[mt], ad + TILE_F * 4);
            }
#pragma unroll
            for (int nt = 0; nt < 4; nt++) {
                uint32_t bd = bhb + (b_lane + (uint32_t)(nt * 8 * LDA + ks * 8)) * 4;
                LDSM2(bh[nt], bd);
                LDSM2(bl[nt], bd + TILE_F * 4);
            }
#pragma unroll
            for (int mt = 0; mt < 4; mt++)
#pragma unroll
                for (int nt = 0; nt < 4; nt++) {
                    mma_tf32(acc[mt][nt], ah[mt], bh[nt]);
                    mma_tf32(acc[mt][nt], ah[mt], bl[nt]);
                    mma_tf32(acc[mt][nt], al[mt], bh[nt]);
                }
        }
    };

    // pipeline
    loadA(0);
    loadB(0, 0);
    CP_COMMIT();
    storeA(0);
    CP_WAIT0();
    __syncthreads();
    for (int c = 0; c < NC; c++) {
        const int s = c & 1, ns = s ^ 1;
        if (c + 1 < NC) {
            loadA(c + 1);
            loadB(c + 1, ns);
            CP_COMMIT();
        }
        compute(s);
        if (c + 1 < NC) {
            storeA(ns);
            CP_WAIT0();
        }
        __syncthreads();
    }

    // epilogue
#pragma unroll
    for (int mt = 0; mt < 4; mt++) {
#pragma unroll
        for (int nt = 0; nt < 4; nt++) {
            const int r0 = bm + wm * 64 + mt * 16 + (lane >> 2);
            const int cb = bn + wn * 32 + nt * 8 + (lane & 3) * 2;
            const float b0 = bias[cb] * bscale;
            const float b1 = bias[cb + 1] * bscale;
#pragma unroll
            for (int half = 0; half < 2; half++) {
                const int r = r0 + half * 8;
                if (r >= rows) continue;
                const float v0 = acc[mt][nt][half * 2 + 0] + b0;
                const float v1 = acc[mt][nt][half * 2 + 1] + b1;
                float2 o = make_float2(lrelu(v0), lrelu(v1));
                const size_t base = (size_t)r * HH + cb;
                if (out_act) *(float2*)(out_act + base) = o;
                if (out_next) {
                    float2 nx = o;
                    if (addend) {
                        float2 ad = *(const float2*)(addend + base);
                        nx.x += ad.x; nx.y += ad.y;
                    }
                    *(float2*)(out_next + base) = nx;
                }
            }
        }
    }
}

// ---------------- weight prep: transpose + tf32 split ----------------
__global__ void prep_conv(const float* __restrict__ W1, int K1,
                          const float* __restrict__ W2, int K2,
                          float* __restrict__ wh, float* __restrict__ wl)
{
    const int Kt  = K1 + K2;
    const int idx = blockIdx.x * 256 + threadIdx.x;
    if (idx >= 256 * Kt) return;
    const int n = idx / Kt, k = idx % Kt;
    const float v = (k < K1) ? W1[(size_t)k * 256 + n] : W2[(size_t)(k - K1) * 256 + n];
    const float h = tf32_hi(v);
    wh[idx] = h;
    wl[idx] = v - h;
}

__global__ void prep_head(const float* __restrict__ w0,
                          float* __restrict__ wh, float* __restrict__ wl)
{
    const int idx = blockIdx.x * 256 + threadIdx.x;
    const int n = idx >> 8, k = idx & 255;
    const float v = w0[(size_t)k * 256 + n] + w0[(size_t)(k + 256) * 256 + n];
    const float h = tf32_hi(v);
    wh[idx] = h;
    wl[idx] = v - h;
}

// ---------------- zero ----------------
__global__ void zero_kernel(float* __restrict__ p, long n)
{
    long i = ((long)blockIdx.x * blockDim.x + threadIdx.x) << 2;
    if (i < n) *(float4*)(p + i) = make_float4(0.f, 0.f, 0.f, 0.f);
}

// ---------------- scatter ----------------
__global__ void scatter_kernel(const float* __restrict__ z, const int* __restrict__ ei,
                               float* __restrict__ agg, int F, int shift)
{
    long tid = (long)blockIdx.x * blockDim.x + threadIdx.x;
    long e   = tid >> shift;
    if (e >= EE) return;
    int f    = (int)(tid & ((1 << shift) - 1)) << 2;
    int sidx = ei[e];
    int d    = ei[EE + e];
    float4 v = *(const float4*)(z + (size_t)sidx * F + f);
    const float* a = agg + (size_t)d * F + f;
    asm volatile("red.global.add.v4.f32 [%0], {%1, %2, %3, %4};"
                 :: "l"(a), "f"(v.x), "f"(v.y), "f"(v.z), "f"(v.w)
                 : "memory");
}

// ---------------- gather ----------------
__global__ void gather_kernel(const float* __restrict__ z, const int* __restrict__ etp,
                              float* __restrict__ s)
{
    long tid = (long)blockIdx.x * blockDim.x + threadIdx.x;
    long e   = tid >> 6;
    if (e >= EPN) return;
    int f = (int)(tid & 63) << 2;
    int a = etp[e * 2 + 0];
    int b = etp[e * 2 + 1];
    float4 va = *(const float4*)(z + (size_t)a * HH + f);
    float4 vb = *(const float4*)(z + (size_t)b * HH + f);
    va.x += vb.x; va.y += vb.y; va.z += vb.z; va.w += vb.w;
    *(float4*)(s + (size_t)e * HH + f) = va;
}

// ---------------- projection ----------------
__global__ void proj_kernel(const float* __restrict__ h, const float* __restrict__ w,
                            const float* __restrict__ b, float* __restrict__ out,
                            int M, int rows)
{
    int gw   = (int)(((long)blockIdx.x * blockDim.x + threadIdx.x) >> 5);
    int lane = threadIdx.x & 31;
    if (gw >= rows) return;
    const float* hr = h + (size_t)gw * HH;
    float a0 = 0.f, a1 = 0.f, a2 = 0.f;
    int k0 = lane << 3;
#pragma unroll
    for (int i = 0; i < 8; i++) {
        int k    = k0 + i;
        float hv = hr[k];
        a0 += hv * w[k * M + 0];
        if (M > 1) {
            a1 += hv * w[k * M + 1];
            a2 += hv * w[k * M + 2];
        }
    }
#pragma unroll
    for (int off = 16; off; off >>= 1) {
        a0 += __shfl_xor_sync(0xffffffffu, a0, off);
        a1 += __shfl_xor_sync(0xffffffffu, a1, off);
        a2 += __shfl_xor_sync(0xffffffffu, a2, off);
    }
    if (lane == 0) {
        out[(size_t)gw * M + 0] = a0 + b[0];
        if (M > 1) {
            out[(size_t)gw * M + 1] = a1 + b[1];
            out[(size_t)gw * M + 2] = a2 + b[2];
        }
    }
}

// ---------------- launch ----------------
extern "C" void kernel_launch(void* const* d_in, const int* in_sizes, int n_in,
                              void* d_out, int out_size)
{
    const float* x   = (const float*)d_in[0];
    const int*   ei  = (const int*)d_in[1];
    const int*   etp = (const int*)d_in[2];
    const float* wrel[4]  = {(const float*)d_in[3],  (const float*)d_in[6],
                             (const float*)d_in[9],  (const float*)d_in[12]};
    const float* brel[4]  = {(const float*)d_in[4],  (const float*)d_in[7],
                             (const float*)d_in[10], (const float*)d_in[13]};
    const float* wroot[4] = {(const float*)d_in[5],  (const float*)d_in[8],
                             (const float*)d_in[11], (const float*)d_in[14]};
    const float* wb0 = (const float*)d_in[15];
    const float* bb0 = (const float*)d_in[16];
    const float* wb1 = (const float*)d_in[17];
    const float* bb1 = (const float*)d_in[18];
    const float* wo0 = (const float*)d_in[19];
    const float* bo0 = (const float*)d_in[20];
    const float* wo1 = (const float*)d_in[21];
    const float* bo1 = (const float*)d_in[22];
    float* out = (float*)d_out;

    float *agg, *zinA, *zinB, *zactA, *zactB, *s, *h;
    float *wth, *wtl, *wtBh, *wtBl, *wtOh, *wtOl;
    cudaGetSymbolAddress((void**)&agg,   g_agg);
    cudaGetSymbolAddress((void**)&zinA,  g_zinA);
    cudaGetSymbolAddress((void**)&zinB,  g_zinB);
    cudaGetSymbolAddress((void**)&zactA, g_zactA);
    cudaGetSymbolAddress((void**)&zactB, g_zactB);
    cudaGetSymbolAddress((void**)&s,     g_s);
    cudaGetSymbolAddress((void**)&h,     g_h);
    cudaGetSymbolAddress((void**)&wth,   g_wt_hi);
    cudaGetSymbolAddress((void**)&wtl,   g_wt_lo);
    cudaGetSymbolAddress((void**)&wtBh,  g_wtB_hi);
    cudaGetSymbolAddress((void**)&wtBl,  g_wtB_lo);
    cudaGetSymbolAddress((void**)&wtOh,  g_wtO_hi);
    cudaGetSymbolAddress((void**)&wtOl,  g_wtO_lo);

    cudaFuncSetAttribute(gemm_mma, cudaFuncAttributeMaxDynamicSharedMemorySize, GM_SMEM);

    dim3 gconv((NN + 127) / 128, 2);
    dim3 ghead((EPN + 127) / 128, 2);

    long z128 = (long)NN * 128, z256 = (long)NN * 256;
    int  zb128 = (int)((z128 / 4 + 255) / 256);
    int  zb256 = (int)((z256 / 4 + 255) / 256);
    int  sc128 = (int)(((long)EE * 32 + 255) / 256);
    int  sc256 = (int)(((long)EE * 64 + 255) / 256);

    // Layer 0: z0 = act(agg(x)@wr0 + b0 + x@wroot0); zinA = z0; zactA = z0
    prep_conv<<<(256 * 256 + 255) / 256, 256>>>(wrel[0], 128, wroot[0], 128, wth, wtl);
    zero_kernel<<<zb128, 256>>>(agg, z128);
    scatter_kernel<<<sc128, 256>>>(x, ei, agg, 128, 5);
    gemm_mma<<<gconv, 256, GM_SMEM>>>(agg, x, 128, 256, wth, wtl, brel[0], 1.f,
                                      nullptr, zactA, zinA, NN);
    // Layer 1: z1; zinB = z1 + z0; zactB = z1
    prep_conv<<<(256 * 512 + 255) / 256, 256>>>(wrel[1], 256, wroot[1], 256, wth, wtl);
    zero_kernel<<<zb256, 256>>>(agg, z256);
    scatter_kernel<<<sc256, 256>>>(zinA, ei, agg, 256, 6);
    gemm_mma<<<gconv, 256, GM_SMEM>>>(agg, zinA, 256, 512, wth, wtl, brel[1], 1.f,
                                      zactA, zactB, zinB, NN);
    // Layer 2: z2; zinA = z2 + z1; zactA = z2
    prep_conv<<<(256 * 512 + 255) / 256, 256>>>(wrel[2], 256, wroot[2], 256, wth, wtl);
    zero_kernel<<<zb256, 256>>>(agg, z256);
    scatter_kernel<<<sc256, 256>>>(zinB, ei, agg, 256, 6);
    gemm_mma<<<gconv, 256, GM_SMEM>>>(agg, zinB, 256, 512, wth, wtl, brel[2], 1.f,
                                      zactB, zactA, zinA, NN);
    // Layer 3: z3; zinB = z3 + z2 (addend = zactA)
    prep_conv<<<(256 * 512 + 255) / 256, 256>>>(wrel[3], 256, wroot[3], 256, wth, wtl);
    zero_kernel<<<zb256, 256>>>(agg, z256);
    scatter_kernel<<<sc256, 256>>>(zinA, ei, agg, 256, 6);
    gemm_mma<<<gconv, 256, GM_SMEM>>>(agg, zinA, 256, 512, wth, wtl, brel[3], 1.f,
                                      zactA, nullptr, zinB, NN);

    // Edge features: s = z[a] + z[b]
    gather_kernel<<<(int)(((long)EPN * 64 + 255) / 256), 256>>>(zinB, etp, s);

    // Heads
    prep_head<<<(256 * 256 + 255) / 256, 256>>>(wb0, wtBh, wtBl);
    prep_head<<<(256 * 256 + 255) / 256, 256>>>(wo0, wtOh, wtOl);
    gemm_mma<<<ghead, 256, GM_SMEM>>>(s, s, 256, 256, wtBh, wtBl, bb0, 2.f,
                                      nullptr, h, nullptr, EPN);
    proj_kernel<<<(int)(((long)EPN * 32 + 255) / 256), 256>>>(h, wb1, bb1,
                                                              out + 3 * EPN, 1, EPN);
    gemm_mma<<<ghead, 256, GM_SMEM>>>(s, s, 256, 256, wtOh, wtOl, bo0, 2.f,
                                      nullptr, h, nullptr, EPN);
    proj_kernel<<<(int)(((long)EPN * 32 + 255) / 256), 256>>>(h, wo1, bo1,
                                                              out, 3, EPN);
}

// round 13
// speedup vs baseline: 1.0043x; 1.0042x over previous
#include <cuda_runtime.h>
#include <cstdint>

#define NN 200000
#define EE 400000
#define EPN 100000
#define HH 256

// ---------------- device scratch ----------------
__device__ float g_agg[(size_t)NN * HH];
__device__ float g_zinA[(size_t)NN * HH];
__device__ float g_zinB[(size_t)NN * HH];
__device__ float g_zactA[(size_t)NN * HH];
__device__ float g_zactB[(size_t)NN * HH];
__device__ float g_s[(size_t)EPN * HH];
__device__ float g_h[(size_t)EPN * HH];
__device__ float g_wt_hi[256 * 512];
__device__ float g_wt_lo[256 * 512];
__device__ float g_wtB_hi[256 * 256];
__device__ float g_wtB_lo[256 * 256];
__device__ float g_wtO_hi[256 * 256];
__device__ float g_wtO_lo[256 * 256];

// ---------------- helpers ----------------
__device__ __forceinline__ float lrelu(float v) { return v >= 0.f ? v : 0.01f * v; }
__device__ __forceinline__ float tf32_hi(float a) {
    return __uint_as_float(__float_as_uint(a) & 0xFFFFE000u);
}
__device__ __forceinline__ uint32_t smem_u32(const void* p) {
    uint32_t a;
    asm("{ .reg .u64 t; cvta.to.shared.u64 t, %1; cvt.u32.u64 %0, t; }" : "=r"(a) : "l"(p));
    return a;
}
__device__ __forceinline__ void cpasync16(uint32_t dst, const void* src) {
    asm volatile("cp.async.ca.shared.global [%0], [%1], 16;" :: "r"(dst), "l"(src));
}
#define CP_COMMIT() asm volatile("cp.async.commit_group;" ::: "memory")
#define CP_WAIT0()  asm volatile("cp.async.wait_group 0;" ::: "memory")

#define LDSM4(r, a)                                                            \
    asm volatile("ldmatrix.sync.aligned.m8n8.x4.shared.b16 {%0,%1,%2,%3}, [%4];" \
                 : "=r"((r)[0]), "=r"((r)[1]), "=r"((r)[2]), "=r"((r)[3]) : "r"(a))
#define LDSM2(r, a)                                                            \
    asm volatile("ldmatrix.sync.aligned.m8n8.x2.shared.b16 {%0,%1}, [%2];"     \
                 : "=r"((r)[0]), "=r"((r)[1]) : "r"(a))

__device__ __forceinline__ void mma_tf32(float* d, const uint32_t* a, const uint32_t* b) {
    asm volatile("mma.sync.aligned.m16n8k8.row.col.f32.tf32.tf32.f32 "
                 "{%0,%1,%2,%3},{%4,%5,%6,%7},{%8,%9},{%0,%1,%2,%3};"
                 : "+f"(d[0]), "+f"(d[1]), "+f"(d[2]), "+f"(d[3])
                 : "r"(a[0]), "r"(a[1]), "r"(a[2]), "r"(a[3]), "r"(b[0]), "r"(b[1]));
}

// ---------------- 3xTF32 mma.sync GEMM ----------------
// C[rows x 256] = act([A1|A2] @ WT^T + bias*bscale); WT pre-split [256][Kt] k-contig
#define BK 32
#define LDA 36
#define TILE_F (128 * LDA)       // 4608 floats
#define STAGE_F (4 * TILE_F)     // Ah, Al, Bh, Bl
#define GM_SMEM (2 * STAGE_F * 4)

__global__ void __launch_bounds__(256, 1) gemm_mma(
    const float* __restrict__ A1, const float* __restrict__ A2,
    int K1, int Kt,
    const float* __restrict__ WTh, const float* __restrict__ WTl,
    const float* __restrict__ bias, float bscale,
    const float* __restrict__ addend,
    float* __restrict__ out_act, float* __restrict__ out_next,
    int rows)
{
    extern __shared__ float sm[];
    const int tid  = threadIdx.x;
    const int lane = tid & 31;
    const int wid  = tid >> 5;
    const int wm   = wid & 1;       // 2 warps along M (64 rows each)
    const int wn   = wid >> 1;      // 4 warps along N (32 cols each)
    const int bm   = blockIdx.x * 128;
    const int bn   = blockIdx.y * 128;
    const int NC   = Kt >> 5;
    const int K2   = Kt - K1;

    const uint32_t smb = smem_u32(sm);

    // A gmem load mapping: thread -> (row, 16-float half)
    const int arow  = tid >> 1;
    const int acolb = (tid & 1) * 16;
    const int grow  = bm + arow;
    const bool rowok = grow < rows;

    // ldmatrix lane offsets (floats)
    const int aq = lane >> 3, ar = lane & 7;
    const uint32_t a_lane = (uint32_t)((wm * 64 + (aq & 1) * 8 + ar) * LDA + (aq >> 1) * 4);
    const int t4 = lane & 15;
    const uint32_t b_lane = (uint32_t)((wn * 32 + (t4 & 7)) * LDA + (t4 >> 3) * 4);

    float acc[4][4][4];
#pragma unroll
    for (int mt = 0; mt < 4; mt++)
#pragma unroll
        for (int nt = 0; nt < 4; nt++)
#pragma unroll
            for (int j = 0; j < 4; j++) acc[mt][nt][j] = 0.f;

    float4 areg[4];

    auto loadA = [&](int c) {
        const int k0 = c * BK;
        const float* Ap;
        int stride, koff;
        if (k0 < K1) { Ap = A1; stride = K1; koff = k0; }
        else         { Ap = A2; stride = K2; koff = k0 - K1; }
        const float* src = Ap + (size_t)grow * stride + koff + acolb;
#pragma unroll
        for (int j = 0; j < 4; j++)
            areg[j] = rowok ? *(const float4*)(src + j * 4)
                            : make_float4(0.f, 0.f, 0.f, 0.f);
    };
    auto storeA = [&](int s) {
        float* Ah = sm + s * STAGE_F;
        float* Al = Ah + TILE_F;
        const int doff = arow * LDA + acolb;
#pragma unroll
        for (int j = 0; j < 4; j++) {
            float4 v = areg[j], h, l;
            h.x = tf32_hi(v.x); l.x = v.x - h.x;
            h.y = tf32_hi(v.y); l.y = v.y - h.y;
            h.z = tf32_hi(v.z); l.z = v.z - h.z;
            h.w = tf32_hi(v.w); l.w = v.w - h.w;
            *(float4*)(Ah + doff + j * 4) = h;
            *(float4*)(Al + doff + j * 4) = l;
        }
    };
    auto loadB = [&](int c, int s) {
        const int k0 = c * BK;
        const uint32_t bhb = smb + (uint32_t)((s * STAGE_F + 2 * TILE_F) * 4);
        const uint32_t blb = bhb + TILE_F * 4;
#pragma unroll
        for (int i = 0; i < 4; i++) {
            int q = i * 256 + tid;          // 0..1023
            int row = q >> 3, c16 = q & 7;
            size_t goff = (size_t)(bn + row) * Kt + k0 + c16 * 4;
            uint32_t doff = (uint32_t)((row * LDA + c16 * 4) * 4);
            cpasync16(bhb + doff, WTh + goff);
            cpasync16(blb + doff, WTl + goff);
        }
    };
    auto compute = [&](int s) {
        const uint32_t ahb = smb + (uint32_t)(s * STAGE_F * 4);
        const uint32_t bhb = ahb + (uint32_t)(2 * TILE_F * 4);
#pragma unroll
        for (int ks = 0; ks < 4; ks++) {
            uint32_t ah[4][4], al[4][4], bh[4][2], bl[4][2];
#pragma unroll
            for (int mt = 0; mt < 4; mt++) {
                uint32_t ad = ahb + (a_lane + (uint32_t)(mt * 16 * LDA + ks * 8)) * 4;
                LDSM4(ah[mt], ad);
                LDSM4(al[mt], ad + TILE_F * 4);
            }
#pragma unroll
            for (int nt = 0; nt < 4; nt++) {
                uint32_t bd = bhb + (b_lane + (uint32_t)(nt * 8 * LDA + ks * 8)) * 4;
                LDSM2(bh[nt], bd);
                LDSM2(bl[nt], bd + TILE_F * 4);
            }
#pragma unroll
            for (int mt = 0; mt < 4; mt++)
#pragma unroll
                for (int nt = 0; nt < 4; nt++) {
                    mma_tf32(acc[mt][nt], ah[mt], bh[nt]);
                    mma_tf32(acc[mt][nt], ah[mt], bl[nt]);
                    mma_tf32(acc[mt][nt], al[mt], bh[nt]);
                }
        }
    };

    // pipeline
    loadA(0);
    loadB(0, 0);
    CP_COMMIT();
    storeA(0);
    CP_WAIT0();
    __syncthreads();
    for (int c = 0; c < NC; c++) {
        const int s = c & 1, ns = s ^ 1;
        if (c + 1 < NC) {
            loadA(c + 1);
            loadB(c + 1, ns);
            CP_COMMIT();
        }
        compute(s);
        if (c + 1 < NC) {
            storeA(ns);
            CP_WAIT0();
        }
        __syncthreads();
    }

    // epilogue
#pragma unroll
    for (int mt = 0; mt < 4; mt++) {
#pragma unroll
        for (int nt = 0; nt < 4; nt++) {
            const int r0 = bm + wm * 64 + mt * 16 + (lane >> 2);
            const int cb = bn + wn * 32 + nt * 8 + (lane & 3) * 2;
            const float b0 = bias[cb] * bscale;
            const float b1 = bias[cb + 1] * bscale;
#pragma unroll
            for (int half = 0; half < 2; half++) {
                const int r = r0 + half * 8;
                if (r >= rows) continue;
                const float v0 = acc[mt][nt][half * 2 + 0] + b0;
                const float v1 = acc[mt][nt][half * 2 + 1] + b1;
                float2 o = make_float2(lrelu(v0), lrelu(v1));
                const size_t base = (size_t)r * HH + cb;
                if (out_act) *(float2*)(out_act + base) = o;
                if (out_next) {
                    float2 nx = o;
                    if (addend) {
                        float2 ad = *(const float2*)(addend + base);
                        nx.x += ad.x; nx.y += ad.y;
                    }
                    *(float2*)(out_next + base) = nx;
                }
            }
        }
    }
}

// ---------------- weight prep: transpose + tf32 split ----------------
__global__ void prep_conv(const float* __restrict__ W1, int K1,
                          const float* __restrict__ W2, int K2,
                          float* __restrict__ wh, float* __restrict__ wl)
{
    const int Kt  = K1 + K2;
    const int idx = blockIdx.x * 256 + threadIdx.x;
    if (idx >= 256 * Kt) return;
    const int n = idx / Kt, k = idx % Kt;
    const float v = (k < K1) ? W1[(size_t)k * 256 + n] : W2[(size_t)(k - K1) * 256 + n];
    const float h = tf32_hi(v);
    wh[idx] = h;
    wl[idx] = v - h;
}

__global__ void prep_head(const float* __restrict__ w0,
                          float* __restrict__ wh, float* __restrict__ wl)
{
    const int idx = blockIdx.x * 256 + threadIdx.x;
    const int n = idx >> 8, k = idx & 255;
    const float v = w0[(size_t)k * 256 + n] + w0[(size_t)(k + 256) * 256 + n];
    const float h = tf32_hi(v);
    wh[idx] = h;
    wl[idx] = v - h;
}

// ---------------- zero ----------------
__global__ void zero_kernel(float* __restrict__ p, long n)
{
    long i = ((long)blockIdx.x * blockDim.x + threadIdx.x) << 2;
    if (i < n) *(float4*)(p + i) = make_float4(0.f, 0.f, 0.f, 0.f);
}

// ---------------- scatter ----------------
__global__ void scatter_kernel(const float* __restrict__ z, const int* __restrict__ ei,
                               float* __restrict__ agg, int F, int shift)
{
    long tid = (long)blockIdx.x * blockDim.x + threadIdx.x;
    long e   = tid >> shift;
    if (e >= EE) return;
    int f    = (int)(tid & ((1 << shift) - 1)) << 2;
    int sidx = ei[e];
    int d    = ei[EE + e];
    float4 v = *(const float4*)(z + (size_t)sidx * F + f);
    const float* a = agg + (size_t)d * F + f;
    asm volatile("red.global.add.v4.f32 [%0], {%1, %2, %3, %4};"
                 :: "l"(a), "f"(v.x), "f"(v.y), "f"(v.z), "f"(v.w)
                 : "memory");
}

// ---------------- gather ----------------
__global__ void gather_kernel(const float* __restrict__ z, const int* __restrict__ etp,
                              float* __restrict__ s)
{
    long tid = (long)blockIdx.x * blockDim.x + threadIdx.x;
    long e   = tid >> 6;
    if (e >= EPN) return;
    int f = (int)(tid & 63) << 2;
    int a = etp[e * 2 + 0];
    int b = etp[e * 2 + 1];
    float4 va = *(const float4*)(z + (size_t)a * HH + f);
    float4 vb = *(const float4*)(z + (size_t)b * HH + f);
    va.x += vb.x; va.y += vb.y; va.z += vb.z; va.w += vb.w;
    *(float4*)(s + (size_t)e * HH + f) = va;
}

// ---------------- projection ----------------
__global__ void proj_kernel(const float* __restrict__ h, const float* __restrict__ w,
                            const float* __restrict__ b, float* __restrict__ out,
                            int M, int rows)
{
    int gw   = (int)(((long)blockIdx.x * blockDim.x + threadIdx.x) >> 5);
    int lane = threadIdx.x & 31;
    if (gw >= rows) return;
    const float* hr = h + (size_t)gw * HH;
    float a0 = 0.f, a1 = 0.f, a2 = 0.f;
    int k0 = lane << 3;
#pragma unroll
    for (int i = 0; i < 8; i++) {
        int k    = k0 + i;
        float hv = hr[k];
        a0 += hv * w[k * M + 0];
        if (M > 1) {
            a1 += hv * w[k * M + 1];
            a2 += hv * w[k * M + 2];
        }
    }
#pragma unroll
    for (int off = 16; off; off >>= 1) {
        a0 += __shfl_xor_sync(0xffffffffu, a0, off);
        a1 += __shfl_xor_sync(0xffffffffu, a1, off);
        a2 += __shfl_xor_sync(0xffffffffu, a2, off);
    }
    if (lane == 0) {
        out[(size_t)gw * M + 0] = a0 + b[0];
        if (M > 1) {
            out[(size_t)gw * M + 1] = a1 + b[1];
            out[(size_t)gw * M + 2] = a2 + b[2];
        }
    }
}

// ---------------- launch ----------------
extern "C" void kernel_launch(void* const* d_in, const int* in_sizes, int n_in,
                              void* d_out, int out_size)
{
    const float* x   = (const float*)d_in[0];
    const int*   ei  = (const int*)d_in[1];
    const int*   etp = (const int*)d_in[2];
    const float* wrel[4]  = {(const float*)d_in[3],  (const float*)d_in[6],
                             (const float*)d_in[9],  (const float*)d_in[12]};
    const float* brel[4]  = {(const float*)d_in[4],  (const float*)d_in[7],
                             (const float*)d_in[10], (const float*)d_in[13]};
    const float* wroot[4] = {(const float*)d_in[5],  (const float*)d_in[8],
                             (const float*)d_in[11], (const float*)d_in[14]};
    const float* wb0 = (const float*)d_in[15];
    const float* bb0 = (const float*)d_in[16];
    const float* wb1 = (const float*)d_in[17];
    const float* bb1 = (const float*)d_in[18];
    const float* wo0 = (const float*)d_in[19];
    const float* bo0 = (const float*)d_in[20];
    const float* wo1 = (const float*)d_in[21];
    const float* bo1 = (const float*)d_in[22];
    float* out = (float*)d_out;

    float *agg, *zinA, *zinB, *zactA, *zactB, *s, *h;
    float *wth, *wtl, *wtBh, *wtBl, *wtOh, *wtOl;
    cudaGetSymbolAddress((void**)&agg,   g_agg);
    cudaGetSymbolAddress((void**)&zinA,  g_zinA);
    cudaGetSymbolAddress((void**)&zinB,  g_zinB);
    cudaGetSymbolAddress((void**)&zactA, g_zactA);
    cudaGetSymbolAddress((void**)&zactB, g_zactB);
    cudaGetSymbolAddress((void**)&s,     g_s);
    cudaGetSymbolAddress((void**)&h,     g_h);
    cudaGetSymbolAddress((void**)&wth,   g_wt_hi);
    cudaGetSymbolAddress((void**)&wtl,   g_wt_lo);
    cudaGetSymbolAddress((void**)&wtBh,  g_wtB_hi);
    cudaGetSymbolAddress((void**)&wtBl,  g_wtB_lo);
    cudaGetSymbolAddress((void**)&wtOh,  g_wtO_hi);
    cudaGetSymbolAddress((void**)&wtOl,  g_wtO_lo);

    cudaFuncSetAttribute(gemm_mma, cudaFuncAttributeMaxDynamicSharedMemorySize, GM_SMEM);

    dim3 gconv((NN + 127) / 128, 2);
    dim3 ghead((EPN + 127) / 128, 2);

    long z128 = (long)NN * 128, z256 = (long)NN * 256;
    int  zb128 = (int)((z128 / 4 + 255) / 256);
    int  zb256 = (int)((z256 / 4 + 255) / 256);
    int  sc128 = (int)(((long)EE * 32 + 255) / 256);
    int  sc256 = (int)(((long)EE * 64 + 255) / 256);

    // Layer 0: z0 = act(agg(x)@wr0 + b0 + x@wroot0); zinA = z0; zactA = z0
    prep_conv<<<(256 * 256 + 255) / 256, 256>>>(wrel[0], 128, wroot[0], 128, wth, wtl);
    zero_kernel<<<zb128, 256>>>(agg, z128);
    scatter_kernel<<<sc128, 256>>>(x, ei, agg, 128, 5);
    gemm_mma<<<gconv, 256, GM_SMEM>>>(agg, x, 128, 256, wth, wtl, brel[0], 1.f,
                                      nullptr, zactA, zinA, NN);
    // Layer 1: z1; zinB = z1 + z0; zactB = z1
    prep_conv<<<(256 * 512 + 255) / 256, 256>>>(wrel[1], 256, wroot[1], 256, wth, wtl);
    zero_kernel<<<zb256, 256>>>(agg, z256);
    scatter_kernel<<<sc256, 256>>>(zinA, ei, agg, 256, 6);
    gemm_mma<<<gconv, 256, GM_SMEM>>>(agg, zinA, 256, 512, wth, wtl, brel[1], 1.f,
                                      zactA, zactB, zinB, NN);
    // Layer 2: z2; zinA = z2 + z1; zactA = z2
    prep_conv<<<(256 * 512 + 255) / 256, 256>>>(wrel[2], 256, wroot[2], 256, wth, wtl);
    zero_kernel<<<zb256, 256>>>(agg, z256);
    scatter_kernel<<<sc256, 256>>>(zinB, ei, agg, 256, 6);
    gemm_mma<<<gconv, 256, GM_SMEM>>>(agg, zinB, 256, 512, wth, wtl, brel[2], 1.f,
                                      zactB, zactA, zinA, NN);
    // Layer 3: z3; zinB = z3 + z2 (addend = zactA)
    prep_conv<<<(256 * 512 + 255) / 256, 256>>>(wrel[3], 256, wroot[3], 256, wth, wtl);
    zero_kernel<<<zb256, 256>>>(agg, z256);
    scatter_kernel<<<sc256, 256>>>(zinA, ei, agg, 256, 6);
    gemm_mma<<<gconv, 256, GM_SMEM>>>(agg, zinA, 256, 512, wth, wtl, brel[3], 1.f,
                                      zactA, nullptr, zinB, NN);

    // Edge features: s = z[a] + z[b]
    gather_kernel<<<(int)(((long)EPN * 64 + 255) / 256), 256>>>(zinB, etp, s);

    // Heads
    prep_head<<<(256 * 256 + 255) / 256, 256>>>(wb0, wtBh, wtBl);
    prep_head<<<(256 * 256 + 255) / 256, 256>>>(wo0, wtOh, wtOl);
    gemm_mma<<<ghead, 256, GM_SMEM>>>(s, s, 256, 256, wtBh, wtBl, bb0, 2.f,
                                      nullptr, h, nullptr, EPN);
    proj_kernel<<<(int)(((long)EPN * 32 + 255) / 256), 256>>>(h, wb1, bb1,
                                                              out + 3 * EPN, 1, EPN);
    gemm_mma<<<ghead, 256, GM_SMEM>>>(s, s, 256, 256, wtOh, wtOl, bo0, 2.f,
                                      nullptr, h, nullptr, EPN);
    proj_kernel<<<(int)(((long)EPN * 32 + 255) / 256), 256>>>(h, wo1, bo1,
                                                              out, 3, EPN);
}

// round 14
// speedup vs baseline: 1.0044x; 1.0000x over previous
#include <cuda_runtime.h>
#include <cstdint>

#define NN 200000
#define EE 400000
#define EPN 100000
#define HH 256

// ---------------- device scratch ----------------
__device__ float g_agg[(size_t)NN * HH];
__device__ float g_zinA[(size_t)NN * HH];
__device__ float g_zinB[(size_t)NN * HH];
__device__ float g_zactA[(size_t)NN * HH];
__device__ float g_zactB[(size_t)NN * HH];
__device__ float g_s[(size_t)EPN * HH];
__device__ float g_h[(size_t)EPN * HH];
__device__ float g_wt_hi[256 * 512];
__device__ float g_wt_lo[256 * 512];
__device__ float g_wtB_hi[256 * 256];
__device__ float g_wtB_lo[256 * 256];
__device__ float g_wtO_hi[256 * 256];
__device__ float g_wtO_lo[256 * 256];

// ---------------- helpers ----------------
__device__ __forceinline__ float lrelu(float v) { return v >= 0.f ? v : 0.01f * v; }
__device__ __forceinline__ float tf32_hi(float a) {
    return __uint_as_float(__float_as_uint(a) & 0xFFFFE000u);
}
__device__ __forceinline__ uint32_t smem_u32(const void* p) {
    uint32_t a;
    asm("{ .reg .u64 t; cvta.to.shared.u64 t, %1; cvt.u32.u64 %0, t; }" : "=r"(a) : "l"(p));
    return a;
}
__device__ __forceinline__ void cpasync16(uint32_t dst, const void* src) {
    asm volatile("cp.async.ca.shared.global [%0], [%1], 16;" :: "r"(dst), "l"(src));
}
#define CP_COMMIT() asm volatile("cp.async.commit_group;" ::: "memory")
#define CP_WAIT0()  asm volatile("cp.async.wait_group 0;" ::: "memory")

#define LDSM4(r, a)                                                            \
    asm volatile("ldmatrix.sync.aligned.m8n8.x4.shared.b16 {%0,%1,%2,%3}, [%4];" \
                 : "=r"((r)[0]), "=r"((r)[1]), "=r"((r)[2]), "=r"((r)[3]) : "r"(a))
#define LDSM2(r, a)                                                            \
    asm volatile("ldmatrix.sync.aligned.m8n8.x2.shared.b16 {%0,%1}, [%2];"     \
                 : "=r"((r)[0]), "=r"((r)[1]) : "r"(a))

__device__ __forceinline__ void mma_tf32(float* d, const uint32_t* a, const uint32_t* b) {
    asm volatile("mma.sync.aligned.m16n8k8.row.col.f32.tf32.tf32.f32 "
                 "{%0,%1,%2,%3},{%4,%5,%6,%7},{%8,%9},{%0,%1,%2,%3};"
                 : "+f"(d[0]), "+f"(d[1]), "+f"(d[2]), "+f"(d[3])
                 : "r"(a[0]), "r"(a[1]), "r"(a[2]), "r"(a[3]), "r"(b[0]), "r"(b[1]));
}

// ---------------- 3xTF32 mma.sync GEMM ----------------
// C[rows x 256] = act([A1|A2] @ WT^T + bias*bscale); WT pre-split [256][Kt] k-contig
#define BK 32
#define LDA 36
#define TILE_F (128 * LDA)       // 4608 floats
#define STAGE_F (4 * TILE_F)     // Ah, Al, Bh, Bl
#define GM_SMEM (2 * STAGE_F * 4)

__global__ void __launch_bounds__(256, 1) gemm_mma(
    const float* __restrict__ A1, const float* __restrict__ A2,
    int K1, int Kt,
    const float* __restrict__ WTh, const float* __restrict__ WTl,
    const float* __restrict__ bias, float bscale,
    const float* __restrict__ addend,
    float* __restrict__ out_act, float* __restrict__ out_next,
    int rows)
{
    extern __shared__ float sm[];
    const int tid  = threadIdx.x;
    const int lane = tid & 31;
    const int wid  = tid >> 5;
    const int wm   = wid & 1;       // 2 warps along M (64 rows each)
    const int wn   = wid >> 1;      // 4 warps along N (32 cols each)
    const int bm   = blockIdx.x * 128;
    const int bn   = blockIdx.y * 128;
    const int NC   = Kt >> 5;
    const int K2   = Kt - K1;

    const uint32_t smb = smem_u32(sm);

    // A gmem load mapping: thread -> (row, 16-float half)
    const int arow  = tid >> 1;
    const int acolb = (tid & 1) * 16;
    const int grow  = bm + arow;
    const bool rowok = grow < rows;

    // ldmatrix lane offsets (floats)
    const int aq = lane >> 3, ar = lane & 7;
    const uint32_t a_lane = (uint32_t)((wm * 64 + (aq & 1) * 8 + ar) * LDA + (aq >> 1) * 4);
    const int t4 = lane & 15;
    const uint32_t b_lane = (uint32_t)((wn * 32 + (t4 & 7)) * LDA + (t4 >> 3) * 4);

    float acc[4][4][4];
#pragma unroll
    for (int mt = 0; mt < 4; mt++)
#pragma unroll
        for (int nt = 0; nt < 4; nt++)
#pragma unroll
            for (int j = 0; j < 4; j++) acc[mt][nt][j] = 0.f;

    float4 areg[4];

    auto loadA = [&](int c) {
        const int k0 = c * BK;
        const float* Ap;
        int stride, koff;
        if (k0 < K1) { Ap = A1; stride = K1; koff = k0; }
        else         { Ap = A2; stride = K2; koff = k0 - K1; }
        const float* src = Ap + (size_t)grow * stride + koff + acolb;
#pragma unroll
        for (int j = 0; j < 4; j++)
            areg[j] = rowok ? *(const float4*)(src + j * 4)
                            : make_float4(0.f, 0.f, 0.f, 0.f);
    };
    auto storeA = [&](int s) {
        float* Ah = sm + s * STAGE_F;
        float* Al = Ah + TILE_F;
        const int doff = arow * LDA + acolb;
#pragma unroll
        for (int j = 0; j < 4; j++) {
            float4 v = areg[j], h, l;
            h.x = tf32_hi(v.x); l.x = v.x - h.x;
            h.y = tf32_hi(v.y); l.y = v.y - h.y;
            h.z = tf32_hi(v.z); l.z = v.z - h.z;
            h.w = tf32_hi(v.w); l.w = v.w - h.w;
            *(float4*)(Ah + doff + j * 4) = h;
            *(float4*)(Al + doff + j * 4) = l;
        }
    };
    auto loadB = [&](int c, int s) {
        const int k0 = c * BK;
        const uint32_t bhb = smb + (uint32_t)((s * STAGE_F + 2 * TILE_F) * 4);
        const uint32_t blb = bhb + TILE_F * 4;
#pragma unroll
        for (int i = 0; i < 4; i++) {
            int q = i * 256 + tid;          // 0..1023
            int row = q >> 3, c16 = q & 7;
            size_t goff = (size_t)(bn + row) * Kt + k0 + c16 * 4;
            uint32_t doff = (uint32_t)((row * LDA + c16 * 4) * 4);
            cpasync16(bhb + doff, WTh + goff);
            cpasync16(blb + doff, WTl + goff);
        }
    };
    auto compute = [&](int s) {
        const uint32_t ahb = smb + (uint32_t)(s * STAGE_F * 4);
        const uint32_t bhb = ahb + (uint32_t)(2 * TILE_F * 4);
#pragma unroll
        for (int ks = 0; ks < 4; ks++) {
            uint32_t ah[4][4], al[4][4], bh[4][2], bl[4][2];
#pragma unroll
            for (int mt = 0; mt < 4; mt++) {
                uint32_t ad = ahb + (a_lane + (uint32_t)(mt * 16 * LDA + ks * 8)) * 4;
                LDSM4(ah[mt], ad);
                LDSM4(al[mt], ad + TILE_F * 4);
            }
#pragma unroll
            for (int nt = 0; nt < 4; nt++) {
                uint32_t bd = bhb + (b_lane + (uint32_t)(nt * 8 * LDA + ks * 8)) * 4;
                LDSM2(bh[nt], bd);
                LDSM2(bl[nt], bd + TILE_F * 4);
            }
#pragma unroll
            for (int mt = 0; mt < 4; mt++)
#pragma unroll
                for (int nt = 0; nt < 4; nt++) {
                    mma_tf32(acc[mt][nt], ah[mt], bh[nt]);
                    mma_tf32(acc[mt][nt], ah[mt], bl[nt]);
                    mma_tf32(acc[mt][nt], al[mt], bh[nt]);
                }
        }
    };

    // pipeline
    loadA(0);
    loadB(0, 0);
    CP_COMMIT();
    storeA(0);
    CP_WAIT0();
    __syncthreads();
    for (int c = 0; c < NC; c++) {
        const int s = c & 1, ns = s ^ 1;
        if (c + 1 < NC) {
            loadA(c + 1);
            loadB(c + 1, ns);
            CP_COMMIT();
        }
        compute(s);
        if (c + 1 < NC) {
            storeA(ns);
            CP_WAIT0();
        }
        __syncthreads();
    }

    // epilogue
#pragma unroll
    for (int mt = 0; mt < 4; mt++) {
#pragma unroll
        for (int nt = 0; nt < 4; nt++) {
            const int r0 = bm + wm * 64 + mt * 16 + (lane >> 2);
            const int cb = bn + wn * 32 + nt * 8 + (lane & 3) * 2;
            const float b0 = bias[cb] * bscale;
            const float b1 = bias[cb + 1] * bscale;
#pragma unroll
            for (int half = 0; half < 2; half++) {
                const int r = r0 + half * 8;
                if (r >= rows) continue;
                const float v0 = acc[mt][nt][half * 2 + 0] + b0;
                const float v1 = acc[mt][nt][half * 2 + 1] + b1;
                float2 o = make_float2(lrelu(v0), lrelu(v1));
                const size_t base = (size_t)r * HH + cb;
                if (out_act) *(float2*)(out_act + base) = o;
                if (out_next) {
                    float2 nx = o;
                    if (addend) {
                        float2 ad = *(const float2*)(addend + base);
                        nx.x += ad.x; nx.y += ad.y;
                    }
                    *(float2*)(out_next + base) = nx;
                }
            }
        }
    }
}

// ---------------- weight prep: transpose + tf32 split ----------------
__global__ void prep_conv(const float* __restrict__ W1, int K1,
                          const float* __restrict__ W2, int K2,
                          float* __restrict__ wh, float* __restrict__ wl)
{
    const int Kt  = K1 + K2;
    const int idx = blockIdx.x * 256 + threadIdx.x;
    if (idx >= 256 * Kt) return;
    const int n = idx / Kt, k = idx % Kt;
    const float v = (k < K1) ? W1[(size_t)k * 256 + n] : W2[(size_t)(k - K1) * 256 + n];
    const float h = tf32_hi(v);
    wh[idx] = h;
    wl[idx] = v - h;
}

__global__ void prep_head(const float* __restrict__ w0,
                          float* __restrict__ wh, float* __restrict__ wl)
{
    const int idx = blockIdx.x * 256 + threadIdx.x;
    const int n = idx >> 8, k = idx & 255;
    const float v = w0[(size_t)k * 256 + n] + w0[(size_t)(k + 256) * 256 + n];
    const float h = tf32_hi(v);
    wh[idx] = h;
    wl[idx] = v - h;
}

// ---------------- zero ----------------
__global__ void zero_kernel(float* __restrict__ p, long n)
{
    long i = ((long)blockIdx.x * blockDim.x + threadIdx.x) << 2;
    if (i < n) *(float4*)(p + i) = make_float4(0.f, 0.f, 0.f, 0.f);
}

// ---------------- scatter ----------------
__global__ void scatter_kernel(const float* __restrict__ z, const int* __restrict__ ei,
                               float* __restrict__ agg, int F, int shift)
{
    long tid = (long)blockIdx.x * blockDim.x + threadIdx.x;
    long e   = tid >> shift;
    if (e >= EE) return;
    int f    = (int)(tid & ((1 << shift) - 1)) << 2;
    int sidx = ei[e];
    int d    = ei[EE + e];
    float4 v = *(const float4*)(z + (size_t)sidx * F + f);
    const float* a = agg + (size_t)d * F + f;
    asm volatile("red.global.add.v4.f32 [%0], {%1, %2, %3, %4};"
                 :: "l"(a), "f"(v.x), "f"(v.y), "f"(v.z), "f"(v.w)
                 : "memory");
}

// ---------------- gather ----------------
__global__ void gather_kernel(const float* __restrict__ z, const int* __restrict__ etp,
                              float* __restrict__ s)
{
    long tid = (long)blockIdx.x * blockDim.x + threadIdx.x;
    long e   = tid >> 6;
    if (e >= EPN) return;
    int f = (int)(tid & 63) << 2;
    int a = etp[e * 2 + 0];
    int b = etp[e * 2 + 1];
    float4 va = *(const float4*)(z + (size_t)a * HH + f);
    float4 vb = *(const float4*)(z + (size_t)b * HH + f);
    va.x += vb.x; va.y += vb.y; va.z += vb.z; va.w += vb.w;
    *(float4*)(s + (size_t)e * HH + f) = va;
}

// ---------------- projection ----------------
__global__ void proj_kernel(const float* __restrict__ h, const float* __restrict__ w,
                            const float* __restrict__ b, float* __restrict__ out,
                            int M, int rows)
{
    int gw   = (int)(((long)blockIdx.x * blockDim.x + threadIdx.x) >> 5);
    int lane = threadIdx.x & 31;
    if (gw >= rows) return;
    const float* hr = h + (size_t)gw * HH;
    float a0 = 0.f, a1 = 0.f, a2 = 0.f;
    int k0 = lane << 3;
#pragma unroll
    for (int i = 0; i < 8; i++) {
        int k    = k0 + i;
        float hv = hr[k];
        a0 += hv * w[k * M + 0];
        if (M > 1) {
            a1 += hv * w[k * M + 1];
            a2 += hv * w[k * M + 2];
        }
    }
#pragma unroll
    for (int off = 16; off; off >>= 1) {
        a0 += __shfl_xor_sync(0xffffffffu, a0, off);
        a1 += __shfl_xor_sync(0xffffffffu, a1, off);
        a2 += __shfl_xor_sync(0xffffffffu, a2, off);
    }
    if (lane == 0) {
        out[(size_t)gw * M + 0] = a0 + b[0];
        if (M > 1) {
            out[(size_t)gw * M + 1] = a1 + b[1];
            out[(size_t)gw * M + 2] = a2 + b[2];
        }
    }
}

// ---------------- launch ----------------
extern "C" void kernel_launch(void* const* d_in, const int* in_sizes, int n_in,
                              void* d_out, int out_size)
{
    const float* x   = (const float*)d_in[0];
    const int*   ei  = (const int*)d_in[1];
    const int*   etp = (const int*)d_in[2];
    const float* wrel[4]  = {(const float*)d_in[3],  (const float*)d_in[6],
                             (const float*)d_in[9],  (const float*)d_in[12]};
    const float* brel[4]  = {(const float*)d_in[4],  (const float*)d_in[7],
                             (const float*)d_in[10], (const float*)d_in[13]};
    const float* wroot[4] = {(const float*)d_in[5],  (const float*)d_in[8],
                             (const float*)d_in[11], (const float*)d_in[14]};
    const float* wb0 = (const float*)d_in[15];
    const float* bb0 = (const float*)d_in[16];
    const float* wb1 = (const float*)d_in[17];
    const float* bb1 = (const float*)d_in[18];
    const float* wo0 = (const float*)d_in[19];
    const float* bo0 = (const float*)d_in[20];
    const float* wo1 = (const float*)d_in[21];
    const float* bo1 = (const float*)d_in[22];
    float* out = (float*)d_out;

    float *agg, *zinA, *zinB, *zactA, *zactB, *s, *h;
    float *wth, *wtl, *wtBh, *wtBl, *wtOh, *wtOl;
    cudaGetSymbolAddress((void**)&agg,   g_agg);
    cudaGetSymbolAddress((void**)&zinA,  g_zinA);
    cudaGetSymbolAddress((void**)&zinB,  g_zinB);
    cudaGetSymbolAddress((void**)&zactA, g_zactA);
    cudaGetSymbolAddress((void**)&zactB, g_zactB);
    cudaGetSymbolAddress((void**)&s,     g_s);
    cudaGetSymbolAddress((void**)&h,     g_h);
    cudaGetSymbolAddress((void**)&wth,   g_wt_hi);
    cudaGetSymbolAddress((void**)&wtl,   g_wt_lo);
    cudaGetSymbolAddress((void**)&wtBh,  g_wtB_hi);
    cudaGetSymbolAddress((void**)&wtBl,  g_wtB_lo);
    cudaGetSymbolAddress((void**)&wtOh,  g_wtO_hi);
    cudaGetSymbolAddress((void**)&wtOl,  g_wtO_lo);

    cudaFuncSetAttribute(gemm_mma, cudaFuncAttributeMaxDynamicSharedMemorySize, GM_SMEM);

    dim3 gconv((NN + 127) / 128, 2);
    dim3 ghead((EPN + 127) / 128, 2);

    long z128 = (long)NN * 128, z256 = (long)NN * 256;
    int  zb128 = (int)((z128 / 4 + 255) / 256);
    int  zb256 = (int)((z256 / 4 + 255) / 256);
    int  sc128 = (int)(((long)EE * 32 + 255) / 256);
    int  sc256 = (int)(((long)EE * 64 + 255) / 256);

    // Layer 0: z0 = act(agg(x)@wr0 + b0 + x@wroot0); zinA = z0; zactA = z0
    prep_conv<<<(256 * 256 + 255) / 256, 256>>>(wrel[0], 128, wroot[0], 128, wth, wtl);
    zero_kernel<<<zb128, 256>>>(agg, z128);
    scatter_kernel<<<sc128, 256>>>(x, ei, agg, 128, 5);
    gemm_mma<<<gconv, 256, GM_SMEM>>>(agg, x, 128, 256, wth, wtl, brel[0], 1.f,
                                      nullptr, zactA, zinA, NN);
    // Layer 1: z1; zinB = z1 + z0; zactB = z1
    prep_conv<<<(256 * 512 + 255) / 256, 256>>>(wrel[1], 256, wroot[1], 256, wth, wtl);
    zero_kernel<<<zb256, 256>>>(agg, z256);
    scatter_kernel<<<sc256, 256>>>(zinA, ei, agg, 256, 6);
    gemm_mma<<<gconv, 256, GM_SMEM>>>(agg, zinA, 256, 512, wth, wtl, brel[1], 1.f,
                                      zactA, zactB, zinB, NN);
    // Layer 2: z2; zinA = z2 + z1; zactA = z2
    prep_conv<<<(256 * 512 + 255) / 256, 256>>>(wrel[2], 256, wroot[2], 256, wth, wtl);
    zero_kernel<<<zb256, 256>>>(agg, z256);
    scatter_kernel<<<sc256, 256>>>(zinB, ei, agg, 256, 6);
    gemm_mma<<<gconv, 256, GM_SMEM>>>(agg, zinB, 256, 512, wth, wtl, brel[2], 1.f,
                                      zactB, zactA, zinA, NN);
    // Layer 3: z3; zinB = z3 + z2 (addend = zactA)
    prep_conv<<<(256 * 512 + 255) / 256, 256>>>(wrel[3], 256, wroot[3], 256, wth, wtl);
    zero_kernel<<<zb256, 256>>>(agg, z256);
    scatter_kernel<<<sc256, 256>>>(zinA, ei, agg, 256, 6);
    gemm_mma<<<gconv, 256, GM_SMEM>>>(agg, zinA, 256, 512, wth, wtl, brel[3], 1.f,
                                      zactA, nullptr, zinB, NN);

    // Edge features: s = z[a] + z[b]
    gather_kernel<<<(int)(((long)EPN * 64 + 255) / 256), 256>>>(zinB, etp, s);

    // Heads
    prep_head<<<(256 * 256 + 255) / 256, 256>>>(wb0, wtBh, wtBl);
    prep_head<<<(256 * 256 + 255) / 256, 256>>>(wo0, wtOh, wtOl);
    gemm_mma<<<ghead, 256, GM_SMEM>>>(s, s, 256, 256, wtBh, wtBl, bb0, 2.f,
                                      nullptr, h, nullptr, EPN);
    proj_kernel<<<(int)(((long)EPN * 32 + 255) / 256), 256>>>(h, wb1, bb1,
                                                              out + 3 * EPN, 1, EPN);
    gemm_mma<<<ghead, 256, GM_SMEM>>>(s, s, 256, 256, wtOh, wtOl, bo0, 2.f,
                                      nullptr, h, nullptr, EPN);
    proj_kernel<<<(int)(((long)EPN * 32 + 255) / 256), 256>>>(h, wo1, bo1,
                                                              out, 3, EPN);
}